// round 15
// baseline (speedup 1.0000x reference)
#include <cuda_runtime.h>
#include <cuda_fp16.h>
#include <math.h>
#include <stdint.h>

#define NN 8192
#define FIN 256
#define DD 128
#define ALPHA 0.2f
#define SPLITS 16
#define BM 128
#define BN 64
#define TILES ((NN / SPLITS) / BN)   // 8
#define LOG2E 1.44269504f
#define MASKV (-100000.f)

// Scratch (allocation-free rule: __device__ globals).
__device__ uint4 gHh[(size_t)NN * 16];
__device__ uint4 gHl[(size_t)NN * 16];
__device__ uint4 gKh[(size_t)NN * 16];
__device__ uint4 gKl[(size_t)NN * 16];
__device__ uint4 gV[(size_t)NN * 16];
__device__ uint4 gIh[(size_t)NN * 32];
__device__ uint4 gIl[(size_t)NN * 32];
__device__ uint4 gWh[3 * 256 * 16];
__device__ uint4 gWl[3 * 256 * 16];
// O partials as packed half2: [split][row][64 half2]. 32 MB.
__device__ uint32_t gNum2[(size_t)SPLITS * NN * 64];
__device__ float gDen[(size_t)SPLITS * NN];
__device__ float gM[(size_t)SPLITS * NN];   // running max, log2 units
__device__ int gCnt[NN / BM];               // split-k fixup counters

// ---------------------------------------------------------------------------
// helpers
// ---------------------------------------------------------------------------
__device__ __forceinline__ uint32_t smem_u32(const void* p) {
  uint32_t a;
  asm("{ .reg .u64 t; cvta.to.shared.u64 t, %1; cvt.u32.u64 %0, t; }"
      : "=r"(a) : "l"(p));
  return a;
}
__device__ __forceinline__ uint32_t pack_h2(float a, float b) {
  __half2 r = __floats2half2_rn(a, b);
  return *reinterpret_cast<uint32_t*>(&r);
}
__device__ __forceinline__ float h_round(float x) {
  return __half2float(__float2half_rn(x));
}
__device__ __forceinline__ float ex2f(float x) {
  float r;
  asm("ex2.approx.f32 %0, %1;" : "=f"(r) : "f"(x));
  return r;
}

#define LDSM_X4(r0, r1, r2, r3, a)                                            \
  asm volatile("ldmatrix.sync.aligned.m8n8.x4.shared.b16 {%0,%1,%2,%3}, [%4];"\
               : "=r"(r0), "=r"(r1), "=r"(r2), "=r"(r3) : "r"(a))
#define LDSM_X4T(r0, r1, r2, r3, a)                                           \
  asm volatile("ldmatrix.sync.aligned.m8n8.x4.trans.shared.b16 {%0,%1,%2,%3}, [%4];" \
               : "=r"(r0), "=r"(r1), "=r"(r2), "=r"(r3) : "r"(a))

__device__ __forceinline__ void mma_f16(float* d, const uint32_t* a,
                                        uint32_t b0, uint32_t b1) {
  asm volatile(
      "mma.sync.aligned.m16n8k16.row.col.f32.f16.f16.f32 "
      "{%0,%1,%2,%3}, {%4,%5,%6,%7}, {%8,%9}, {%0,%1,%2,%3};"
      : "+f"(d[0]), "+f"(d[1]), "+f"(d[2]), "+f"(d[3])
      : "r"(a[0]), "r"(a[1]), "r"(a[2]), "r"(a[3]), "r"(b0), "r"(b1));
}

__device__ __forceinline__ void cp16(uint32_t dst, const void* src) {
  asm volatile("cp.async.cg.shared.global [%0], [%1], 16;" :: "r"(dst), "l"(src));
}
#define CP_COMMIT() asm volatile("cp.async.commit_group;" ::: "memory")
#define CP_WAIT1()  asm volatile("cp.async.wait_group 1;" ::: "memory")

// ---------------------------------------------------------------------------
// Kernel 0: split fp32 inputs into packed fp16 hi/lo planes; zero counters.
// ---------------------------------------------------------------------------
__global__ __launch_bounds__(256) void split_kernel(
    const float* __restrict__ inp, const float* __restrict__ W0,
    const float* __restrict__ W1, const float* __restrict__ W2) {
  int idx = blockIdx.x * 256 + threadIdx.x;
  if (blockIdx.x == 0 && threadIdx.x < NN / BM) gCnt[threadIdx.x] = 0;
  const float* src;
  uint32_t* dh;
  uint32_t* dl;
  int off;
  if (idx < 1048576) {
    src = inp; off = idx;
    dh = (uint32_t*)gIh; dl = (uint32_t*)gIl;
  } else {
    int j = idx - 1048576;
    int mat = j / 16384;
    off = j % 16384;
    src = (mat == 0) ? W0 : (mat == 1) ? W1 : W2;
    dh = (uint32_t*)gWh + mat * 16384;
    dl = (uint32_t*)gWl + mat * 16384;
  }
  float2 v = *(const float2*)(src + 2 * (size_t)off);
  float h0 = h_round(v.x);
  float h1 = h_round(v.y);
  dh[off] = pack_h2(h0, h1);
  dl[off] = pack_h2(v.x - h0, v.y - h1);
}

// ---------------------------------------------------------------------------
// Kernel A: projections via warp mma.sync fp16 hi/lo (3-term).
// ---------------------------------------------------------------------------
#define PSTG 27648
#define PSMEM 55296
__global__ void __launch_bounds__(128, 1) proj_kernel() {
  extern __shared__ char smem[];
  uint32_t sb = smem_u32(smem);
  int t = threadIdx.x, w = t >> 5, lane = t & 31;
  int g = lane >> 2, tig = lane & 3;
  int q = lane >> 3, r = lane & 7;
  int rowbase = blockIdx.x * 64;
  int mat = blockIdx.y;
  const uint4* Wh = gWh + mat * 256 * 16;
  const uint4* Wl = gWl + mat * 256 * 16;

  uint32_t offA = (uint32_t)((w * 16 + (q & 1) * 8 + r) * 80 + (q >> 1) * 16);
  uint32_t offB = (uint32_t)(10240 + ((q & 1) * 8 + r) * 272 + (q >> 1) * 16);

  auto load_chunk = [&](int s, int c) {
    uint32_t base = sb + (uint32_t)(s * PSTG);
#pragma unroll
    for (int i = 0; i < 4; i++) {
      int idx = t + i * 128;
      int plane = idx >> 8, row = (idx >> 2) & 63, ch = idx & 3;
      const uint4* srcp = (plane ? gIl : gIh) + (size_t)(rowbase + row) * 32 + c * 4 + ch;
      cp16(base + plane * 5120 + row * 80 + ch * 16, srcp);
    }
#pragma unroll
    for (int i = 0; i < 8; i++) {
      int idx = t + i * 128;
      int plane = idx >> 9, row = (idx >> 4) & 31, ch = idx & 15;
      const uint4* srcp = (plane ? Wl : Wh) + (size_t)(c * 32 + row) * 16 + ch;
      cp16(base + 10240 + plane * 8704 + row * 272 + ch * 16, srcp);
    }
  };

  load_chunk(0, 0); CP_COMMIT();
  load_chunk(1, 1); CP_COMMIT();

  float oacc[16][4];
#pragma unroll
  for (int c = 0; c < 16; c++)
#pragma unroll
    for (int k = 0; k < 4; k++) oacc[c][k] = 0.f;

  for (int c = 0; c < 8; c++) {
    int s = c & 1;
    CP_WAIT1();
    __syncthreads();
    uint32_t aA = sb + (uint32_t)(s * PSTG) + offA;
    uint32_t aB = sb + (uint32_t)(s * PSTG) + offB;
#pragma unroll
    for (int kk = 0; kk < 2; kk++) {
      uint32_t ah[4], al[4];
      LDSM_X4(ah[0], ah[1], ah[2], ah[3], aA + kk * 32);
      LDSM_X4(al[0], al[1], al[2], al[3], aA + 5120 + kk * 32);
#pragma unroll
      for (int np = 0; np < 8; np++) {
        uint32_t bh[4], bl[4];
        uint32_t boff = (uint32_t)(kk * 4352 + np * 32);
        LDSM_X4T(bh[0], bh[1], bh[2], bh[3], aB + boff);
        LDSM_X4T(bl[0], bl[1], bl[2], bl[3], aB + 8704 + boff);
        mma_f16(oacc[2 * np], ah, bh[0], bh[1]);
        mma_f16(oacc[2 * np], ah, bl[0], bl[1]);
        mma_f16(oacc[2 * np], al, bh[0], bh[1]);
        mma_f16(oacc[2 * np + 1], ah, bh[2], bh[3]);
        mma_f16(oacc[2 * np + 1], ah, bl[2], bl[3]);
        mma_f16(oacc[2 * np + 1], al, bh[2], bh[3]);
      }
    }
    __syncthreads();
    if (c + 2 < 8) load_chunk(s, c + 2);
    CP_COMMIT();
  }

  int row0 = rowbase + w * 16 + g;
  size_t r0w = (size_t)row0 * 64;
  size_t r8w = r0w + 8 * 64;
  if (mat == 2) {
    uint32_t* Pv = (uint32_t*)gV;
#pragma unroll
    for (int np = 0; np < 8; np++) {
#pragma unroll
      for (int half = 0; half < 2; half++) {
        float* d = oacc[2 * np + half];
        int word = np * 8 + half * 4 + tig;
        Pv[r0w + word] = pack_h2(d[0], d[1]);
        Pv[r8w + word] = pack_h2(d[2], d[3]);
      }
    }
  } else {
    uint32_t* Ph = (uint32_t*)(mat ? gKh : gHh);
    uint32_t* Pl = (uint32_t*)(mat ? gKl : gHl);
#pragma unroll
    for (int np = 0; np < 8; np++) {
#pragma unroll
      for (int half = 0; half < 2; half++) {
        float* d = oacc[2 * np + half];
        int word = np * 8 + half * 4 + tig;
        float h0 = h_round(d[0]);
        float h1 = h_round(d[1]);
        float h2 = h_round(d[2]);
        float h3 = h_round(d[3]);
        Ph[r0w + word] = pack_h2(h0, h1);
        Pl[r0w + word] = pack_h2(d[0] - h0, d[1] - h1);
        Ph[r8w + word] = pack_h2(h2, h3);
        Pl[r8w + word] = pack_h2(d[2] - h2, d[3] - h3);
      }
    }
  }
}

// ---------------------------------------------------------------------------
// Kernel B: fused attention + split-k fixup epilogue.
// Stage: Khi 0 / Klo 17408 / V 34816; 64 rows, stride 272; stage 52224.
// ---------------------------------------------------------------------------
#define TRS 272
#define STAGE 52224
#define SMEM_BYTES 156672           // 3 stages

__device__ __forceinline__ void load_kv_async(uint32_t sb, int s, int cb, int t) {
  uint32_t base = sb + (uint32_t)(s * STAGE);
#pragma unroll
  for (int i = 0; i < 12; i++) {
    int idx = t + i * 256;                 // 0..3071
    if (idx < 2048) {
      int plane = idx >> 10, row = (idx >> 4) & 63, ch = idx & 15;
      const uint4* src = (plane ? gKl : gKh) + (size_t)(cb + row) * 16 + ch;
      cp16(base + plane * 17408 + row * TRS + ch * 16, src);
    } else {
      int v = idx - 2048;
      int row = (v >> 4) & 63, ch = v & 15;
      cp16(base + 34816 + row * TRS + ch * 16, gV + (size_t)(cb + row) * 16 + ch);
    }
  }
}

__global__ void __launch_bounds__(256, 1) attn_kernel(const int* __restrict__ adj,
                                                      float* __restrict__ out) {
  extern __shared__ char smem[];
  uint32_t sb = smem_u32(smem);
  int t = threadIdx.x, w = t >> 5, lane = t & 31;
  int g = lane >> 2, tig = lane & 3;
  int rowbase = blockIdx.x * BM;
  int colstart = blockIdx.y * (NN / SPLITS);
  int q = lane >> 3, r = lane & 7;
  uint32_t offB = (uint32_t)(((q >> 1) * 8 + r) * TRS + (q & 1) * 16);
  uint32_t offV = (uint32_t)(34816 + ((q & 1) * 8 + r) * TRS + (q >> 1) * 16);
  int row0 = rowbase + w * 16 + g;

  // constant B fragment for the all-ones den column (col 0 lives in lanes 0-3)
  uint32_t bones = (lane < 4) ? 0x3C003C00u : 0u;

  load_kv_async(sb, 0, colstart, t);
  CP_COMMIT();
  load_kv_async(sb, 1, colstart + BN, t);
  CP_COMMIT();

  // H fragments via direct LDG (A-fragment layout == packed word layout)
  uint32_t ahf[8][4], alf[8][4];
  {
    const uint32_t* Hh = (const uint32_t*)gHh;
    const uint32_t* Hl = (const uint32_t*)gHl;
    size_t b0 = (size_t)row0 * 64;
    size_t b8 = b0 + 8 * 64;
#pragma unroll
    for (int kk = 0; kk < 8; kk++) {
      int wd = kk * 8 + tig;
      ahf[kk][0] = Hh[b0 + wd];     ahf[kk][1] = Hh[b8 + wd];
      ahf[kk][2] = Hh[b0 + wd + 4]; ahf[kk][3] = Hh[b8 + wd + 4];
      alf[kk][0] = Hl[b0 + wd];     alf[kk][1] = Hl[b8 + wd];
      alf[kk][2] = Hl[b0 + wd + 4]; alf[kk][3] = Hl[b8 + wd + 4];
    }
  }

  float oacc[16][4];
#pragma unroll
  for (int c = 0; c < 16; c++)
#pragma unroll
    for (int k = 0; k < 4; k++) oacc[c][k] = 0.f;
  float dacc[4] = {0.f, 0.f, 0.f, 0.f};
  float m0 = -90000.f, m1 = -90000.f;     // running max, log2 units

  const int* arow0 = adj + (size_t)row0 * NN;
  const int* arow1 = arow0 + (size_t)8 * NN;

  int s3 = 0;
  for (int tt = 0; tt < TILES; tt++) {
    int cb = colstart + tt * BN;
    CP_WAIT1();
    __syncthreads();
    if (tt + 2 < TILES) load_kv_async(sb, (tt + 2) % 3, colstart + (tt + 2) * BN, t);
    CP_COMMIT();

    int2 am[16];
#pragma unroll
    for (int n = 0; n < 8; n++) {
      am[n] = *(const int2*)(arow0 + cb + n * 8 + 2 * tig);
      am[n + 8] = *(const int2*)(arow1 + cb + n * 8 + 2 * tig);
    }

    uint32_t aBh = sb + (uint32_t)(s3 * STAGE) + offB;
    uint32_t aBl = aBh + 17408;
    uint32_t aVh = sb + (uint32_t)(s3 * STAGE) + offV;

    // ---- S = H @ K^T (fp16 hi/lo: hh + hl + lh), A from registers ----
    float sacc[8][4];
#pragma unroll
    for (int c = 0; c < 8; c++)
#pragma unroll
      for (int k = 0; k < 4; k++) sacc[c][k] = 0.f;

#pragma unroll
    for (int kk = 0; kk < 8; kk++) {
#pragma unroll
      for (int np = 0; np < 4; np++) {
        uint32_t bh[4], bl[4];
        uint32_t boff = (uint32_t)(np * (16 * TRS) + kk * 32);
        LDSM_X4(bh[0], bh[1], bh[2], bh[3], aBh + boff);
        LDSM_X4(bl[0], bl[1], bl[2], bl[3], aBl + boff);
        mma_f16(sacc[2 * np], ahf[kk], bh[0], bh[1]);
        mma_f16(sacc[2 * np], ahf[kk], bl[0], bl[1]);
        mma_f16(sacc[2 * np], alf[kk], bh[0], bh[1]);
        mma_f16(sacc[2 * np + 1], ahf[kk], bh[2], bh[3]);
        mma_f16(sacc[2 * np + 1], ahf[kk], bl[2], bl[3]);
        mma_f16(sacc[2 * np + 1], alf[kk], bh[2], bh[3]);
      }
    }

    // ---- leakyrelu + mask -> log2 args; online max; vote-gated rescale ----
#pragma unroll
    for (int n = 0; n < 8; n++) {
      int2 mA = am[n];
      int2 mB = am[n + 8];
      float s0 = sacc[n][0], s1 = sacc[n][1], s2 = sacc[n][2], s3v = sacc[n][3];
      float a0 = fmaxf(s0, ALPHA * s0) * LOG2E;
      float a1 = fmaxf(s1, ALPHA * s1) * LOG2E;
      float a2 = fmaxf(s2, ALPHA * s2) * LOG2E;
      float a3 = fmaxf(s3v, ALPHA * s3v) * LOG2E;
      sacc[n][0] = (mA.x > 0) ? a0 : MASKV;
      sacc[n][1] = (mA.y > 0) ? a1 : MASKV;
      sacc[n][2] = (mB.x > 0) ? a2 : MASKV;
      sacc[n][3] = (mB.y > 0) ? a3 : MASKV;
    }
    {
      float mt0 = MASKV, mt1 = MASKV;
#pragma unroll
      for (int n = 0; n < 8; n++) {
        mt0 = fmaxf(mt0, fmaxf(sacc[n][0], sacc[n][1]));
        mt1 = fmaxf(mt1, fmaxf(sacc[n][2], sacc[n][3]));
      }
      mt0 = fmaxf(mt0, __shfl_xor_sync(0xffffffffu, mt0, 1));
      mt0 = fmaxf(mt0, __shfl_xor_sync(0xffffffffu, mt0, 2));
      mt1 = fmaxf(mt1, __shfl_xor_sync(0xffffffffu, mt1, 1));
      mt1 = fmaxf(mt1, __shfl_xor_sync(0xffffffffu, mt1, 2));
      float m0n = fmaxf(m0, mt0);
      float m1n = fmaxf(m1, mt1);
      bool need = (m0n > m0) || (m1n > m1);
      if (__any_sync(0xffffffffu, need)) {
        float sc0 = ex2f(m0 - m0n);
        float sc1 = ex2f(m1 - m1n);
#pragma unroll
        for (int c = 0; c < 16; c++) {
          oacc[c][0] *= sc0; oacc[c][1] *= sc0;
          oacc[c][2] *= sc1; oacc[c][3] *= sc1;
        }
        dacc[0] *= sc0; dacc[2] *= sc1;
      }
      m0 = m0n; m1 = m1n;
    }

    // ---- P = ex2(arg - m) -> fp16 fragments -> den MMA + PV ----
#pragma unroll
    for (int kk = 0; kk < 4; kk++) {
      uint32_t pw[4];
#pragma unroll
      for (int cp = 0; cp < 2; cp++) {
        int n = 2 * kk + cp;
        float p0 = ex2f(sacc[n][0] - m0);
        float p1 = ex2f(sacc[n][1] - m0);
        float p2 = ex2f(sacc[n][2] - m1);
        float p3 = ex2f(sacc[n][3] - m1);
        pw[2 * cp + 0] = pack_h2(p0, p1);
        pw[2 * cp + 1] = pack_h2(p2, p3);
      }
      mma_f16(dacc, pw, bones, bones);   // den += P @ ones (col 0)
#pragma unroll
      for (int cp = 0; cp < 8; cp++) {
        uint32_t vv[4];
        uint32_t voff = (uint32_t)(kk * (16 * TRS) + cp * 32);
        LDSM_X4T(vv[0], vv[1], vv[2], vv[3], aVh + voff);
        mma_f16(oacc[2 * cp], pw, vv[0], vv[1]);
        mma_f16(oacc[2 * cp + 1], pw, vv[2], vv[3]);
      }
    }
    s3 = (s3 == 2) ? 0 : s3 + 1;
  }

  // ---- epilogue: den + m + O partials (packed half2) ----
  if (tig == 0) {
    gDen[(size_t)blockIdx.y * NN + row0] = dacc[0];
    gDen[(size_t)blockIdx.y * NN + row0 + 8] = dacc[2];
    gM[(size_t)blockIdx.y * NN + row0] = m0;
    gM[(size_t)blockIdx.y * NN + row0 + 8] = m1;
  }
  {
    size_t p0 = ((size_t)blockIdx.y * NN + row0) * 64;
    size_t p8 = ((size_t)blockIdx.y * NN + row0 + 8) * 64;
#pragma unroll
    for (int c = 0; c < 16; c++) {
      gNum2[p0 + c * 4 + tig] = pack_h2(oacc[c][0], oacc[c][1]);
      gNum2[p8 + c * 4 + tig] = pack_h2(oacc[c][2], oacc[c][3]);
    }
  }

  // ---- split-k fixup: last arriver for this row block combines all splits --
  __threadfence();
  __shared__ int sflag;
  if (t == 0) sflag = atomicAdd(&gCnt[blockIdx.x], 1);
  __syncthreads();
  if (sflag != SPLITS - 1) return;
  __threadfence();

  __shared__ float swgt[SPLITS][BM];   // per-split weights (8 KB)
  __shared__ float sinv[BM];           // 1/den_total
  if (t < BM) {
    int rowg = rowbase + t;
    float ms[SPLITS], M = -1e30f;
#pragma unroll
    for (int s = 0; s < SPLITS; s++) {
      ms[s] = gM[(size_t)s * NN + rowg];
      M = fmaxf(M, ms[s]);
    }
    float den = 0.f;
#pragma unroll
    for (int s = 0; s < SPLITS; s++) {
      float wgt = ex2f(ms[s] - M);
      swgt[s][t] = wgt;
      den += gDen[(size_t)s * NN + rowg] * wgt;
    }
    sinv[t] = 1.f / den;
  }
  __syncthreads();

#pragma unroll
  for (int k2 = 0; k2 < 8; k2++) {
    int cid = t + k2 * 256;            // 0..2047 : (row, 8-col chunk)
    int row = cid >> 4;
    int cc = (cid & 15) * 4;           // half2 index within row (4 half2 = 8 cols)
    float acc[8];
#pragma unroll
    for (int i = 0; i < 8; i++) acc[i] = 0.f;
#pragma unroll
    for (int s = 0; s < SPLITS; s++) {
      uint4 v = *(const uint4*)&gNum2[((size_t)s * NN + rowbase + row) * 64 + cc];
      float wgt = swgt[s][row];
      float2 f0 = __half22float2(*reinterpret_cast<__half2*>(&v.x));
      float2 f1 = __half22float2(*reinterpret_cast<__half2*>(&v.y));
      float2 f2 = __half22float2(*reinterpret_cast<__half2*>(&v.z));
      float2 f3 = __half22float2(*reinterpret_cast<__half2*>(&v.w));
      acc[0] += wgt * f0.x; acc[1] += wgt * f0.y;
      acc[2] += wgt * f1.x; acc[3] += wgt * f1.y;
      acc[4] += wgt * f2.x; acc[5] += wgt * f2.y;
      acc[6] += wgt * f3.x; acc[7] += wgt * f3.y;
    }
    float inv = sinv[row];
    float o[8];
#pragma unroll
    for (int i = 0; i < 8; i++) {
      float h = acc[i] * inv;
      o[i] = (h > 0.f) ? h : expm1f(h);
    }
    float* dst = out + (size_t)(rowbase + row) * DD + cc * 2;
    *(float4*)dst = make_float4(o[0], o[1], o[2], o[3]);
    *(float4*)(dst + 4) = make_float4(o[4], o[5], o[6], o[7]);
  }
}

// ---------------------------------------------------------------------------
extern "C" void kernel_launch(void* const* d_in, const int* in_sizes, int n_in,
                              void* d_out, int out_size) {
  const float* inp = (const float*)d_in[0];
  const int* adj = (const int*)d_in[1];
  const float* W = (const float*)d_in[2];
  const float* W2 = (const float*)d_in[3];
  const float* W3 = (const float*)d_in[4];
  float* out = (float*)d_out;

  split_kernel<<<4288, 256>>>(inp, W, W2, W3);

  cudaFuncSetAttribute(proj_kernel, cudaFuncAttributeMaxDynamicSharedMemorySize,
                       PSMEM);
  proj_kernel<<<dim3(NN / 64, 3), 128, PSMEM>>>();

  cudaFuncSetAttribute(attn_kernel, cudaFuncAttributeMaxDynamicSharedMemorySize,
                       SMEM_BYTES);
  attn_kernel<<<dim3(NN / BM, SPLITS), 256, SMEM_BYTES>>>(adj, out);
}

// round 16
// speedup vs baseline: 1.0810x; 1.0810x over previous
#include <cuda_runtime.h>
#include <cuda_fp16.h>
#include <math.h>
#include <stdint.h>

#define NN 8192
#define FIN 256
#define DD 128
#define ALPHA 0.2f
#define SPLITS 16
#define BM 128
#define BN 64
#define TILES ((NN / SPLITS) / BN)   // 8
#define LOG2E 1.44269504f
#define MASKV (-100000.f)

// Scratch (allocation-free rule: __device__ globals).
__device__ uint4 gHh[(size_t)NN * 16];
__device__ uint4 gHl[(size_t)NN * 16];
__device__ uint4 gKh[(size_t)NN * 16];
__device__ uint4 gKl[(size_t)NN * 16];
__device__ uint4 gV[(size_t)NN * 16];
__device__ uint4 gIh[(size_t)NN * 32];
__device__ uint4 gIl[(size_t)NN * 32];
__device__ uint4 gWh[3 * 256 * 16];
__device__ uint4 gWl[3 * 256 * 16];
// O partials as packed half2: [split][row][64 half2]. 32 MB.
__device__ uint32_t gNum2[(size_t)SPLITS * NN * 64];
__device__ float gDen[(size_t)SPLITS * NN];
__device__ float gM[(size_t)SPLITS * NN];   // running max, log2 units

// ---------------------------------------------------------------------------
// helpers
// ---------------------------------------------------------------------------
__device__ __forceinline__ uint32_t smem_u32(const void* p) {
  uint32_t a;
  asm("{ .reg .u64 t; cvta.to.shared.u64 t, %1; cvt.u32.u64 %0, t; }"
      : "=r"(a) : "l"(p));
  return a;
}
__device__ __forceinline__ uint32_t pack_h2(float a, float b) {
  __half2 r = __floats2half2_rn(a, b);
  return *reinterpret_cast<uint32_t*>(&r);
}
__device__ __forceinline__ float h_round(float x) {
  return __half2float(__float2half_rn(x));
}
__device__ __forceinline__ float ex2f(float x) {
  float r;
  asm("ex2.approx.f32 %0, %1;" : "=f"(r) : "f"(x));
  return r;
}

#define LDSM_X4(r0, r1, r2, r3, a)                                            \
  asm volatile("ldmatrix.sync.aligned.m8n8.x4.shared.b16 {%0,%1,%2,%3}, [%4];"\
               : "=r"(r0), "=r"(r1), "=r"(r2), "=r"(r3) : "r"(a))
#define LDSM_X4T(r0, r1, r2, r3, a)                                           \
  asm volatile("ldmatrix.sync.aligned.m8n8.x4.trans.shared.b16 {%0,%1,%2,%3}, [%4];" \
               : "=r"(r0), "=r"(r1), "=r"(r2), "=r"(r3) : "r"(a))

__device__ __forceinline__ void mma_f16(float* d, const uint32_t* a,
                                        uint32_t b0, uint32_t b1) {
  asm volatile(
      "mma.sync.aligned.m16n8k16.row.col.f32.f16.f16.f32 "
      "{%0,%1,%2,%3}, {%4,%5,%6,%7}, {%8,%9}, {%0,%1,%2,%3};"
      : "+f"(d[0]), "+f"(d[1]), "+f"(d[2]), "+f"(d[3])
      : "r"(a[0]), "r"(a[1]), "r"(a[2]), "r"(a[3]), "r"(b0), "r"(b1));
}

__device__ __forceinline__ void cp16(uint32_t dst, const void* src) {
  asm volatile("cp.async.cg.shared.global [%0], [%1], 16;" :: "r"(dst), "l"(src));
}
#define CP_COMMIT() asm volatile("cp.async.commit_group;" ::: "memory")
#define CP_WAIT1()  asm volatile("cp.async.wait_group 1;" ::: "memory")

// ---------------------------------------------------------------------------
// Kernel 0: split fp32 inputs into packed fp16 hi/lo planes (inp + W).
// ---------------------------------------------------------------------------
__global__ __launch_bounds__(256) void split_kernel(
    const float* __restrict__ inp, const float* __restrict__ W0,
    const float* __restrict__ W1, const float* __restrict__ W2) {
  int idx = blockIdx.x * 256 + threadIdx.x;
  const float* src;
  uint32_t* dh;
  uint32_t* dl;
  int off;
  if (idx < 1048576) {
    src = inp; off = idx;
    dh = (uint32_t*)gIh; dl = (uint32_t*)gIl;
  } else {
    int j = idx - 1048576;
    int mat = j / 16384;
    off = j % 16384;
    src = (mat == 0) ? W0 : (mat == 1) ? W1 : W2;
    dh = (uint32_t*)gWh + mat * 16384;
    dl = (uint32_t*)gWl + mat * 16384;
  }
  float2 v = *(const float2*)(src + 2 * (size_t)off);
  float h0 = h_round(v.x);
  float h1 = h_round(v.y);
  dh[off] = pack_h2(h0, h1);
  dl[off] = pack_h2(v.x - h0, v.y - h1);
}

// ---------------------------------------------------------------------------
// Kernel A: projections via warp mma.sync fp16 hi/lo (3-term).
// ---------------------------------------------------------------------------
#define PSTG 27648
#define PSMEM 55296
__global__ void __launch_bounds__(128, 1) proj_kernel() {
  extern __shared__ char smem[];
  uint32_t sb = smem_u32(smem);
  int t = threadIdx.x, w = t >> 5, lane = t & 31;
  int g = lane >> 2, tig = lane & 3;
  int q = lane >> 3, r = lane & 7;
  int rowbase = blockIdx.x * 64;
  int mat = blockIdx.y;
  const uint4* Wh = gWh + mat * 256 * 16;
  const uint4* Wl = gWl + mat * 256 * 16;

  uint32_t offA = (uint32_t)((w * 16 + (q & 1) * 8 + r) * 80 + (q >> 1) * 16);
  uint32_t offB = (uint32_t)(10240 + ((q & 1) * 8 + r) * 272 + (q >> 1) * 16);

  auto load_chunk = [&](int s, int c) {
    uint32_t base = sb + (uint32_t)(s * PSTG);
#pragma unroll
    for (int i = 0; i < 4; i++) {
      int idx = t + i * 128;
      int plane = idx >> 8, row = (idx >> 2) & 63, ch = idx & 3;
      const uint4* srcp = (plane ? gIl : gIh) + (size_t)(rowbase + row) * 32 + c * 4 + ch;
      cp16(base + plane * 5120 + row * 80 + ch * 16, srcp);
    }
#pragma unroll
    for (int i = 0; i < 8; i++) {
      int idx = t + i * 128;
      int plane = idx >> 9, row = (idx >> 4) & 31, ch = idx & 15;
      const uint4* srcp = (plane ? Wl : Wh) + (size_t)(c * 32 + row) * 16 + ch;
      cp16(base + 10240 + plane * 8704 + row * 272 + ch * 16, srcp);
    }
  };

  load_chunk(0, 0); CP_COMMIT();
  load_chunk(1, 1); CP_COMMIT();

  float oacc[16][4];
#pragma unroll
  for (int c = 0; c < 16; c++)
#pragma unroll
    for (int k = 0; k < 4; k++) oacc[c][k] = 0.f;

  for (int c = 0; c < 8; c++) {
    int s = c & 1;
    CP_WAIT1();
    __syncthreads();
    uint32_t aA = sb + (uint32_t)(s * PSTG) + offA;
    uint32_t aB = sb + (uint32_t)(s * PSTG) + offB;
#pragma unroll
    for (int kk = 0; kk < 2; kk++) {
      uint32_t ah[4], al[4];
      LDSM_X4(ah[0], ah[1], ah[2], ah[3], aA + kk * 32);
      LDSM_X4(al[0], al[1], al[2], al[3], aA + 5120 + kk * 32);
#pragma unroll
      for (int np = 0; np < 8; np++) {
        uint32_t bh[4], bl[4];
        uint32_t boff = (uint32_t)(kk * 4352 + np * 32);
        LDSM_X4T(bh[0], bh[1], bh[2], bh[3], aB + boff);
        LDSM_X4T(bl[0], bl[1], bl[2], bl[3], aB + 8704 + boff);
        mma_f16(oacc[2 * np], ah, bh[0], bh[1]);
        mma_f16(oacc[2 * np], ah, bl[0], bl[1]);
        mma_f16(oacc[2 * np], al, bh[0], bh[1]);
        mma_f16(oacc[2 * np + 1], ah, bh[2], bh[3]);
        mma_f16(oacc[2 * np + 1], ah, bl[2], bl[3]);
        mma_f16(oacc[2 * np + 1], al, bh[2], bh[3]);
      }
    }
    __syncthreads();
    if (c + 2 < 8) load_chunk(s, c + 2);
    CP_COMMIT();
  }

  int row0 = rowbase + w * 16 + g;
  size_t r0w = (size_t)row0 * 64;
  size_t r8w = r0w + 8 * 64;
  if (mat == 2) {
    uint32_t* Pv = (uint32_t*)gV;
#pragma unroll
    for (int np = 0; np < 8; np++) {
#pragma unroll
      for (int half = 0; half < 2; half++) {
        float* d = oacc[2 * np + half];
        int word = np * 8 + half * 4 + tig;
        Pv[r0w + word] = pack_h2(d[0], d[1]);
        Pv[r8w + word] = pack_h2(d[2], d[3]);
      }
    }
  } else {
    uint32_t* Ph = (uint32_t*)(mat ? gKh : gHh);
    uint32_t* Pl = (uint32_t*)(mat ? gKl : gHl);
#pragma unroll
    for (int np = 0; np < 8; np++) {
#pragma unroll
      for (int half = 0; half < 2; half++) {
        float* d = oacc[2 * np + half];
        int word = np * 8 + half * 4 + tig;
        float h0 = h_round(d[0]);
        float h1 = h_round(d[1]);
        float h2 = h_round(d[2]);
        float h3 = h_round(d[3]);
        Ph[r0w + word] = pack_h2(h0, h1);
        Pl[r0w + word] = pack_h2(d[0] - h0, d[1] - h1);
        Ph[r8w + word] = pack_h2(h2, h3);
        Pl[r8w + word] = pack_h2(d[2] - h2, d[3] - h3);
      }
    }
  }
}

// ---------------------------------------------------------------------------
// Kernel B: fused attention, fp16. S = 3-term hi/lo (192 MMA/tile),
// log2-domain online-max softmax, PV single-term (64 MMA/tile),
// den via constant-ones-B MMA (4 MMA/tile). Partials stored as half2.
// Stage: Khi 0 / Klo 17408 / V 34816; 64 rows, stride 272; stage 52224.
// ---------------------------------------------------------------------------
#define TRS 272
#define STAGE 52224
#define SMEM_BYTES 156672           // 3 stages

__device__ __forceinline__ void load_kv_async(uint32_t sb, int s, int cb, int t) {
  uint32_t base = sb + (uint32_t)(s * STAGE);
#pragma unroll
  for (int i = 0; i < 12; i++) {
    int idx = t + i * 256;                 // 0..3071
    if (idx < 2048) {
      int plane = idx >> 10, row = (idx >> 4) & 63, ch = idx & 15;
      const uint4* src = (plane ? gKl : gKh) + (size_t)(cb + row) * 16 + ch;
      cp16(base + plane * 17408 + row * TRS + ch * 16, src);
    } else {
      int v = idx - 2048;
      int row = (v >> 4) & 63, ch = v & 15;
      cp16(base + 34816 + row * TRS + ch * 16, gV + (size_t)(cb + row) * 16 + ch);
    }
  }
}

__global__ void __launch_bounds__(256, 1) attn_kernel(const int* __restrict__ adj) {
  extern __shared__ char smem[];
  uint32_t sb = smem_u32(smem);
  int t = threadIdx.x, w = t >> 5, lane = t & 31;
  int g = lane >> 2, tig = lane & 3;
  int rowbase = blockIdx.x * BM;
  int colstart = blockIdx.y * (NN / SPLITS);
  int q = lane >> 3, r = lane & 7;
  uint32_t offB = (uint32_t)(((q >> 1) * 8 + r) * TRS + (q & 1) * 16);
  uint32_t offV = (uint32_t)(34816 + ((q & 1) * 8 + r) * TRS + (q >> 1) * 16);
  int row0 = rowbase + w * 16 + g;

  // constant B fragment for the all-ones den column (col 0 lives in lanes 0-3)
  uint32_t bones = (lane < 4) ? 0x3C003C00u : 0u;

  load_kv_async(sb, 0, colstart, t);
  CP_COMMIT();
  load_kv_async(sb, 1, colstart + BN, t);
  CP_COMMIT();

  // H fragments via direct LDG (A-fragment layout == packed word layout)
  uint32_t ahf[8][4], alf[8][4];
  {
    const uint32_t* Hh = (const uint32_t*)gHh;
    const uint32_t* Hl = (const uint32_t*)gHl;
    size_t b0 = (size_t)row0 * 64;
    size_t b8 = b0 + 8 * 64;
#pragma unroll
    for (int kk = 0; kk < 8; kk++) {
      int wd = kk * 8 + tig;
      ahf[kk][0] = Hh[b0 + wd];     ahf[kk][1] = Hh[b8 + wd];
      ahf[kk][2] = Hh[b0 + wd + 4]; ahf[kk][3] = Hh[b8 + wd + 4];
      alf[kk][0] = Hl[b0 + wd];     alf[kk][1] = Hl[b8 + wd];
      alf[kk][2] = Hl[b0 + wd + 4]; alf[kk][3] = Hl[b8 + wd + 4];
    }
  }

  float oacc[16][4];
#pragma unroll
  for (int c = 0; c < 16; c++)
#pragma unroll
    for (int k = 0; k < 4; k++) oacc[c][k] = 0.f;
  float dacc[4] = {0.f, 0.f, 0.f, 0.f};
  float m0 = -90000.f, m1 = -90000.f;     // running max, log2 units

  const int* arow0 = adj + (size_t)row0 * NN;
  const int* arow1 = arow0 + (size_t)8 * NN;

  int s3 = 0;
  for (int tt = 0; tt < TILES; tt++) {
    int cb = colstart + tt * BN;
    CP_WAIT1();
    __syncthreads();
    if (tt + 2 < TILES) load_kv_async(sb, (tt + 2) % 3, colstart + (tt + 2) * BN, t);
    CP_COMMIT();

    int2 am[16];
#pragma unroll
    for (int n = 0; n < 8; n++) {
      am[n] = *(const int2*)(arow0 + cb + n * 8 + 2 * tig);
      am[n + 8] = *(const int2*)(arow1 + cb + n * 8 + 2 * tig);
    }

    uint32_t aBh = sb + (uint32_t)(s3 * STAGE) + offB;
    uint32_t aBl = aBh + 17408;
    uint32_t aVh = sb + (uint32_t)(s3 * STAGE) + offV;

    // ---- S = H @ K^T (fp16 hi/lo: hh + hl + lh), A from registers ----
    float sacc[8][4];
#pragma unroll
    for (int c = 0; c < 8; c++)
#pragma unroll
      for (int k = 0; k < 4; k++) sacc[c][k] = 0.f;

#pragma unroll
    for (int kk = 0; kk < 8; kk++) {
#pragma unroll
      for (int np = 0; np < 4; np++) {
        uint32_t bh[4], bl[4];
        uint32_t boff = (uint32_t)(np * (16 * TRS) + kk * 32);
        LDSM_X4(bh[0], bh[1], bh[2], bh[3], aBh + boff);
        LDSM_X4(bl[0], bl[1], bl[2], bl[3], aBl + boff);
        mma_f16(sacc[2 * np], ahf[kk], bh[0], bh[1]);
        mma_f16(sacc[2 * np], ahf[kk], bl[0], bl[1]);
        mma_f16(sacc[2 * np], alf[kk], bh[0], bh[1]);
        mma_f16(sacc[2 * np + 1], ahf[kk], bh[2], bh[3]);
        mma_f16(sacc[2 * np + 1], ahf[kk], bl[2], bl[3]);
        mma_f16(sacc[2 * np + 1], alf[kk], bh[2], bh[3]);
      }
    }

    // ---- leakyrelu + mask -> log2 args; online max; vote-gated rescale ----
#pragma unroll
    for (int n = 0; n < 8; n++) {
      int2 mA = am[n];
      int2 mB = am[n + 8];
      float s0 = sacc[n][0], s1 = sacc[n][1], s2 = sacc[n][2], s3v = sacc[n][3];
      float a0 = fmaxf(s0, ALPHA * s0) * LOG2E;
      float a1 = fmaxf(s1, ALPHA * s1) * LOG2E;
      float a2 = fmaxf(s2, ALPHA * s2) * LOG2E;
      float a3 = fmaxf(s3v, ALPHA * s3v) * LOG2E;
      sacc[n][0] = (mA.x > 0) ? a0 : MASKV;
      sacc[n][1] = (mA.y > 0) ? a1 : MASKV;
      sacc[n][2] = (mB.x > 0) ? a2 : MASKV;
      sacc[n][3] = (mB.y > 0) ? a3 : MASKV;
    }
    {
      float mt0 = MASKV, mt1 = MASKV;
#pragma unroll
      for (int n = 0; n < 8; n++) {
        mt0 = fmaxf(mt0, fmaxf(sacc[n][0], sacc[n][1]));
        mt1 = fmaxf(mt1, fmaxf(sacc[n][2], sacc[n][3]));
      }
      mt0 = fmaxf(mt0, __shfl_xor_sync(0xffffffffu, mt0, 1));
      mt0 = fmaxf(mt0, __shfl_xor_sync(0xffffffffu, mt0, 2));
      mt1 = fmaxf(mt1, __shfl_xor_sync(0xffffffffu, mt1, 1));
      mt1 = fmaxf(mt1, __shfl_xor_sync(0xffffffffu, mt1, 2));
      float m0n = fmaxf(m0, mt0);
      float m1n = fmaxf(m1, mt1);
      bool need = (m0n > m0) || (m1n > m1);
      if (__any_sync(0xffffffffu, need)) {
        float sc0 = ex2f(m0 - m0n);
        float sc1 = ex2f(m1 - m1n);
#pragma unroll
        for (int c = 0; c < 16; c++) {
          oacc[c][0] *= sc0; oacc[c][1] *= sc0;
          oacc[c][2] *= sc1; oacc[c][3] *= sc1;
        }
        dacc[0] *= sc0; dacc[2] *= sc1;
      }
      m0 = m0n; m1 = m1n;
    }

    // ---- P = ex2(arg - m) -> fp16 fragments -> den MMA + PV ----
#pragma unroll
    for (int kk = 0; kk < 4; kk++) {
      uint32_t pw[4];
#pragma unroll
      for (int cp = 0; cp < 2; cp++) {
        int n = 2 * kk + cp;
        float p0 = ex2f(sacc[n][0] - m0);
        float p1 = ex2f(sacc[n][1] - m0);
        float p2 = ex2f(sacc[n][2] - m1);
        float p3 = ex2f(sacc[n][3] - m1);
        pw[2 * cp + 0] = pack_h2(p0, p1);
        pw[2 * cp + 1] = pack_h2(p2, p3);
      }
      mma_f16(dacc, pw, bones, bones);   // den += P @ ones (col 0)
#pragma unroll
      for (int cp = 0; cp < 8; cp++) {
        uint32_t vv[4];
        uint32_t voff = (uint32_t)(kk * (16 * TRS) + cp * 32);
        LDSM_X4T(vv[0], vv[1], vv[2], vv[3], aVh + voff);
        mma_f16(oacc[2 * cp], pw, vv[0], vv[1]);
        mma_f16(oacc[2 * cp + 1], pw, vv[2], vv[3]);
      }
    }
    s3 = (s3 == 2) ? 0 : s3 + 1;
  }

  // ---- epilogue: den (col 0 lives in tig==0 lanes) + m + O partials ----
  if (tig == 0) {
    gDen[(size_t)blockIdx.y * NN + row0] = dacc[0];
    gDen[(size_t)blockIdx.y * NN + row0 + 8] = dacc[2];
    gM[(size_t)blockIdx.y * NN + row0] = m0;
    gM[(size_t)blockIdx.y * NN + row0 + 8] = m1;
  }
  {
    size_t p0 = ((size_t)blockIdx.y * NN + row0) * 64;
    size_t p8 = ((size_t)blockIdx.y * NN + row0 + 8) * 64;
#pragma unroll
    for (int c = 0; c < 16; c++) {
      gNum2[p0 + c * 4 + tig] = pack_h2(oacc[c][0], oacc[c][1]);
      gNum2[p8 + c * 4 + tig] = pack_h2(oacc[c][2], oacc[c][3]);
    }
  }
}

// ---------------------------------------------------------------------------
// Kernel C: combine half2 split partials with per-split max weights (log2),
// divide, ELU. Each thread: one row x 8 cols (uint4 per split).
// ---------------------------------------------------------------------------
__global__ __launch_bounds__(256) void reduce_kernel(float* __restrict__ out) {
  int idx = blockIdx.x * 256 + threadIdx.x;   // over N*D/8 = 131072
  int row = idx >> 4;
  int cc = (idx & 15) * 4;                    // half2 index (4 half2 = 8 cols)
  float ms[SPLITS];
  float M = -1e30f;
#pragma unroll
  for (int s = 0; s < SPLITS; s++) {
    ms[s] = gM[(size_t)s * NN + row];
    M = fmaxf(M, ms[s]);
  }
  float acc[8];
#pragma unroll
  for (int i = 0; i < 8; i++) acc[i] = 0.f;
  float den = 0.f;
#pragma unroll
  for (int s = 0; s < SPLITS; s++) {
    float wgt = ex2f(ms[s] - M);
    uint4 v = *(const uint4*)&gNum2[((size_t)s * NN + row) * 64 + cc];
    float2 f0 = __half22float2(*reinterpret_cast<__half2*>(&v.x));
    float2 f1 = __half22float2(*reinterpret_cast<__half2*>(&v.y));
    float2 f2 = __half22float2(*reinterpret_cast<__half2*>(&v.z));
    float2 f3 = __half22float2(*reinterpret_cast<__half2*>(&v.w));
    acc[0] += wgt * f0.x; acc[1] += wgt * f0.y;
    acc[2] += wgt * f1.x; acc[3] += wgt * f1.y;
    acc[4] += wgt * f2.x; acc[5] += wgt * f2.y;
    acc[6] += wgt * f3.x; acc[7] += wgt * f3.y;
    den += gDen[(size_t)s * NN + row] * wgt;
  }
  float inv = 1.f / den;
  float o[8];
#pragma unroll
  for (int i = 0; i < 8; i++) {
    float h = acc[i] * inv;
    o[i] = (h > 0.f) ? h : expm1f(h);
  }
  float* dst = out + (size_t)row * DD + cc * 2;
  *(float4*)dst = make_float4(o[0], o[1], o[2], o[3]);
  *(float4*)(dst + 4) = make_float4(o[4], o[5], o[6], o[7]);
}

// ---------------------------------------------------------------------------
extern "C" void kernel_launch(void* const* d_in, const int* in_sizes, int n_in,
                              void* d_out, int out_size) {
  const float* inp = (const float*)d_in[0];
  const int* adj = (const int*)d_in[1];
  const float* W = (const float*)d_in[2];
  const float* W2 = (const float*)d_in[3];
  const float* W3 = (const float*)d_in[4];
  float* out = (float*)d_out;

  split_kernel<<<4288, 256>>>(inp, W, W2, W3);

  cudaFuncSetAttribute(proj_kernel, cudaFuncAttributeMaxDynamicSharedMemorySize,
                       PSMEM);
  proj_kernel<<<dim3(NN / 64, 3), 128, PSMEM>>>();

  cudaFuncSetAttribute(attn_kernel, cudaFuncAttributeMaxDynamicSharedMemorySize,
                       SMEM_BYTES);
  attn_kernel<<<dim3(NN / BM, SPLITS), 256, SMEM_BYTES>>>(adj);

  reduce_kernel<<<(NN * DD) / 2048, 256>>>(out);
}

// round 17
// speedup vs baseline: 1.1639x; 1.0766x over previous
#include <cuda_runtime.h>
#include <cuda_fp16.h>
#include <math.h>
#include <stdint.h>

#define NN 8192
#define FIN 256
#define DD 128
#define ALPHA 0.2f
#define SPLITS 16
#define BM 128
#define BN 64
#define TILES ((NN / SPLITS) / BN)   // 8
#define LOG2E 1.44269504f
#define MASKV (-100000.f)

// Scratch (allocation-free rule: __device__ globals).
// H: fp16 hi/lo planes (exact). K, V: single fp16 plane.
__device__ uint4 gHh[(size_t)NN * 16];
__device__ uint4 gHl[(size_t)NN * 16];
__device__ uint4 gK[(size_t)NN * 16];
__device__ uint4 gV[(size_t)NN * 16];
__device__ uint4 gIh[(size_t)NN * 32];
__device__ uint4 gIl[(size_t)NN * 32];
__device__ uint4 gWh[3 * 256 * 16];
__device__ uint4 gWl[3 * 256 * 16];
// O partials as packed half2: [split][row][64 half2]. 32 MB.
__device__ uint32_t gNum2[(size_t)SPLITS * NN * 64];
__device__ float gDen[(size_t)SPLITS * NN];
__device__ float gM[(size_t)SPLITS * NN];   // running max, log2 units

// ---------------------------------------------------------------------------
// helpers
// ---------------------------------------------------------------------------
__device__ __forceinline__ uint32_t smem_u32(const void* p) {
  uint32_t a;
  asm("{ .reg .u64 t; cvta.to.shared.u64 t, %1; cvt.u32.u64 %0, t; }"
      : "=r"(a) : "l"(p));
  return a;
}
__device__ __forceinline__ uint32_t pack_h2(float a, float b) {
  __half2 r = __floats2half2_rn(a, b);
  return *reinterpret_cast<uint32_t*>(&r);
}
__device__ __forceinline__ float h_round(float x) {
  return __half2float(__float2half_rn(x));
}
__device__ __forceinline__ float ex2f(float x) {
  float r;
  asm("ex2.approx.f32 %0, %1;" : "=f"(r) : "f"(x));
  return r;
}

#define LDSM_X4(r0, r1, r2, r3, a)                                            \
  asm volatile("ldmatrix.sync.aligned.m8n8.x4.shared.b16 {%0,%1,%2,%3}, [%4];"\
               : "=r"(r0), "=r"(r1), "=r"(r2), "=r"(r3) : "r"(a))
#define LDSM_X4T(r0, r1, r2, r3, a)                                           \
  asm volatile("ldmatrix.sync.aligned.m8n8.x4.trans.shared.b16 {%0,%1,%2,%3}, [%4];" \
               : "=r"(r0), "=r"(r1), "=r"(r2), "=r"(r3) : "r"(a))

__device__ __forceinline__ void mma_f16(float* d, const uint32_t* a,
                                        uint32_t b0, uint32_t b1) {
  asm volatile(
      "mma.sync.aligned.m16n8k16.row.col.f32.f16.f16.f32 "
      "{%0,%1,%2,%3}, {%4,%5,%6,%7}, {%8,%9}, {%0,%1,%2,%3};"
      : "+f"(d[0]), "+f"(d[1]), "+f"(d[2]), "+f"(d[3])
      : "r"(a[0]), "r"(a[1]), "r"(a[2]), "r"(a[3]), "r"(b0), "r"(b1));
}

__device__ __forceinline__ void cp16(uint32_t dst, const void* src) {
  asm volatile("cp.async.cg.shared.global [%0], [%1], 16;" :: "r"(dst), "l"(src));
}
#define CP_COMMIT() asm volatile("cp.async.commit_group;" ::: "memory")
#define CP_WAIT1()  asm volatile("cp.async.wait_group 1;" ::: "memory")

// ---------------------------------------------------------------------------
// Kernel 0: split fp32 inputs into packed fp16 hi/lo planes (inp + W).
// ---------------------------------------------------------------------------
__global__ __launch_bounds__(256) void split_kernel(
    const float* __restrict__ inp, const float* __restrict__ W0,
    const float* __restrict__ W1, const float* __restrict__ W2) {
  int idx = blockIdx.x * 256 + threadIdx.x;
  const float* src;
  uint32_t* dh;
  uint32_t* dl;
  int off;
  if (idx < 1048576) {
    src = inp; off = idx;
    dh = (uint32_t*)gIh; dl = (uint32_t*)gIl;
  } else {
    int j = idx - 1048576;
    int mat = j / 16384;
    off = j % 16384;
    src = (mat == 0) ? W0 : (mat == 1) ? W1 : W2;
    dh = (uint32_t*)gWh + mat * 16384;
    dl = (uint32_t*)gWl + mat * 16384;
  }
  float2 v = *(const float2*)(src + 2 * (size_t)off);
  float h0 = h_round(v.x);
  float h1 = h_round(v.y);
  dh[off] = pack_h2(h0, h1);
  dl[off] = pack_h2(v.x - h0, v.y - h1);
}

// ---------------------------------------------------------------------------
// Kernel A: projections via warp mma.sync fp16 hi/lo (3-term).
// mat 0 (H): epilogue writes fp16 hi/lo planes (H stays exact in attn).
// mat 1/2 (K/V): epilogue writes single fp16 plane.
// ---------------------------------------------------------------------------
#define PSTG 27648
#define PSMEM 55296
__global__ void __launch_bounds__(128, 1) proj_kernel() {
  extern __shared__ char smem[];
  uint32_t sb = smem_u32(smem);
  int t = threadIdx.x, w = t >> 5, lane = t & 31;
  int g = lane >> 2, tig = lane & 3;
  int q = lane >> 3, r = lane & 7;
  int rowbase = blockIdx.x * 64;
  int mat = blockIdx.y;
  const uint4* Wh = gWh + mat * 256 * 16;
  const uint4* Wl = gWl + mat * 256 * 16;

  uint32_t offA = (uint32_t)((w * 16 + (q & 1) * 8 + r) * 80 + (q >> 1) * 16);
  uint32_t offB = (uint32_t)(10240 + ((q & 1) * 8 + r) * 272 + (q >> 1) * 16);

  auto load_chunk = [&](int s, int c) {
    uint32_t base = sb + (uint32_t)(s * PSTG);
#pragma unroll
    for (int i = 0; i < 4; i++) {
      int idx = t + i * 128;
      int plane = idx >> 8, row = (idx >> 2) & 63, ch = idx & 3;
      const uint4* srcp = (plane ? gIl : gIh) + (size_t)(rowbase + row) * 32 + c * 4 + ch;
      cp16(base + plane * 5120 + row * 80 + ch * 16, srcp);
    }
#pragma unroll
    for (int i = 0; i < 8; i++) {
      int idx = t + i * 128;
      int plane = idx >> 9, row = (idx >> 4) & 31, ch = idx & 15;
      const uint4* srcp = (plane ? Wl : Wh) + (size_t)(c * 32 + row) * 16 + ch;
      cp16(base + 10240 + plane * 8704 + row * 272 + ch * 16, srcp);
    }
  };

  load_chunk(0, 0); CP_COMMIT();
  load_chunk(1, 1); CP_COMMIT();

  float oacc[16][4];
#pragma unroll
  for (int c = 0; c < 16; c++)
#pragma unroll
    for (int k = 0; k < 4; k++) oacc[c][k] = 0.f;

  for (int c = 0; c < 8; c++) {
    int s = c & 1;
    CP_WAIT1();
    __syncthreads();
    uint32_t aA = sb + (uint32_t)(s * PSTG) + offA;
    uint32_t aB = sb + (uint32_t)(s * PSTG) + offB;
#pragma unroll
    for (int kk = 0; kk < 2; kk++) {
      uint32_t ah[4], al[4];
      LDSM_X4(ah[0], ah[1], ah[2], ah[3], aA + kk * 32);
      LDSM_X4(al[0], al[1], al[2], al[3], aA + 5120 + kk * 32);
#pragma unroll
      for (int np = 0; np < 8; np++) {
        uint32_t bh[4], bl[4];
        uint32_t boff = (uint32_t)(kk * 4352 + np * 32);
        LDSM_X4T(bh[0], bh[1], bh[2], bh[3], aB + boff);
        LDSM_X4T(bl[0], bl[1], bl[2], bl[3], aB + 8704 + boff);
        mma_f16(oacc[2 * np], ah, bh[0], bh[1]);
        mma_f16(oacc[2 * np], ah, bl[0], bl[1]);
        mma_f16(oacc[2 * np], al, bh[0], bh[1]);
        mma_f16(oacc[2 * np + 1], ah, bh[2], bh[3]);
        mma_f16(oacc[2 * np + 1], ah, bl[2], bl[3]);
        mma_f16(oacc[2 * np + 1], al, bh[2], bh[3]);
      }
    }
    __syncthreads();
    if (c + 2 < 8) load_chunk(s, c + 2);
    CP_COMMIT();
  }

  int row0 = rowbase + w * 16 + g;
  size_t r0w = (size_t)row0 * 64;
  size_t r8w = r0w + 8 * 64;
  if (mat != 0) {
    // K / V: single fp16 plane
    uint32_t* Pv = (uint32_t*)((mat == 1) ? gK : gV);
#pragma unroll
    for (int np = 0; np < 8; np++) {
#pragma unroll
      for (int half = 0; half < 2; half++) {
        float* d = oacc[2 * np + half];
        int word = np * 8 + half * 4 + tig;
        Pv[r0w + word] = pack_h2(d[0], d[1]);
        Pv[r8w + word] = pack_h2(d[2], d[3]);
      }
    }
  } else {
    // H: fp16 hi/lo planes
    uint32_t* Ph = (uint32_t*)gHh;
    uint32_t* Pl = (uint32_t*)gHl;
#pragma unroll
    for (int np = 0; np < 8; np++) {
#pragma unroll
      for (int half = 0; half < 2; half++) {
        float* d = oacc[2 * np + half];
        int word = np * 8 + half * 4 + tig;
        float h0 = h_round(d[0]);
        float h1 = h_round(d[1]);
        float h2 = h_round(d[2]);
        float h3 = h_round(d[3]);
        Ph[r0w + word] = pack_h2(h0, h1);
        Pl[r0w + word] = pack_h2(d[0] - h0, d[1] - h1);
        Ph[r8w + word] = pack_h2(h2, h3);
        Pl[r8w + word] = pack_h2(d[2] - h2, d[3] - h3);
      }
    }
  }
}

// ---------------------------------------------------------------------------
// Kernel B: fused attention, fp16. S = (Hhi+Hlo)·Khi^T 2-term (128 MMA/tile),
// log2-domain online-max softmax, PV single-term (64 MMA/tile),
// den via constant-ones-B MMA (4 MMA/tile). Partials stored as half2.
// Stage: K 0 / V 17408; 64 rows, stride 272; stage 34816.
// ---------------------------------------------------------------------------
#define TRS 272
#define STAGE 34816
#define SMEM_BYTES 104448           // 3 stages

__device__ __forceinline__ void load_kv_async(uint32_t sb, int s, int cb, int t) {
  uint32_t base = sb + (uint32_t)(s * STAGE);
#pragma unroll
  for (int i = 0; i < 8; i++) {
    int idx = t + i * 256;                 // 0..2047
    if (idx < 1024) {
      int row = (idx >> 4) & 63, ch = idx & 15;
      cp16(base + row * TRS + ch * 16, gK + (size_t)(cb + row) * 16 + ch);
    } else {
      int v = idx - 1024;
      int row = (v >> 4) & 63, ch = v & 15;
      cp16(base + 17408 + row * TRS + ch * 16, gV + (size_t)(cb + row) * 16 + ch);
    }
  }
}

__global__ void __launch_bounds__(256, 1) attn_kernel(const int* __restrict__ adj) {
  extern __shared__ char smem[];
  uint32_t sb = smem_u32(smem);
  int t = threadIdx.x, w = t >> 5, lane = t & 31;
  int g = lane >> 2, tig = lane & 3;
  int rowbase = blockIdx.x * BM;
  int colstart = blockIdx.y * (NN / SPLITS);
  int q = lane >> 3, r = lane & 7;
  uint32_t offB = (uint32_t)(((q >> 1) * 8 + r) * TRS + (q & 1) * 16);
  uint32_t offV = (uint32_t)(17408 + ((q & 1) * 8 + r) * TRS + (q >> 1) * 16);
  int row0 = rowbase + w * 16 + g;

  // constant B fragment for the all-ones den column (col 0 lives in lanes 0-3)
  uint32_t bones = (lane < 4) ? 0x3C003C00u : 0u;

  load_kv_async(sb, 0, colstart, t);
  CP_COMMIT();
  load_kv_async(sb, 1, colstart + BN, t);
  CP_COMMIT();

  // H fragments via direct LDG (A-fragment layout == packed word layout)
  uint32_t ahf[8][4], alf[8][4];
  {
    const uint32_t* Hh = (const uint32_t*)gHh;
    const uint32_t* Hl = (const uint32_t*)gHl;
    size_t b0 = (size_t)row0 * 64;
    size_t b8 = b0 + 8 * 64;
#pragma unroll
    for (int kk = 0; kk < 8; kk++) {
      int wd = kk * 8 + tig;
      ahf[kk][0] = Hh[b0 + wd];     ahf[kk][1] = Hh[b8 + wd];
      ahf[kk][2] = Hh[b0 + wd + 4]; ahf[kk][3] = Hh[b8 + wd + 4];
      alf[kk][0] = Hl[b0 + wd];     alf[kk][1] = Hl[b8 + wd];
      alf[kk][2] = Hl[b0 + wd + 4]; alf[kk][3] = Hl[b8 + wd + 4];
    }
  }

  float oacc[16][4];
#pragma unroll
  for (int c = 0; c < 16; c++)
#pragma unroll
    for (int k = 0; k < 4; k++) oacc[c][k] = 0.f;
  float dacc[4] = {0.f, 0.f, 0.f, 0.f};
  float m0 = -90000.f, m1 = -90000.f;     // running max, log2 units

  const int* arow0 = adj + (size_t)row0 * NN;
  const int* arow1 = arow0 + (size_t)8 * NN;

  int s3 = 0;
  for (int tt = 0; tt < TILES; tt++) {
    int cb = colstart + tt * BN;
    CP_WAIT1();
    __syncthreads();
    if (tt + 2 < TILES) load_kv_async(sb, (tt + 2) % 3, colstart + (tt + 2) * BN, t);
    CP_COMMIT();

    int2 am[16];
#pragma unroll
    for (int n = 0; n < 8; n++) {
      am[n] = *(const int2*)(arow0 + cb + n * 8 + 2 * tig);
      am[n + 8] = *(const int2*)(arow1 + cb + n * 8 + 2 * tig);
    }

    uint32_t aBh = sb + (uint32_t)(s3 * STAGE) + offB;
    uint32_t aVh = sb + (uint32_t)(s3 * STAGE) + offV;

    // ---- S = (Hhi + Hlo) @ Khi^T : 2 MMAs per 8-col block ----
    float sacc[8][4];
#pragma unroll
    for (int c = 0; c < 8; c++)
#pragma unroll
      for (int k = 0; k < 4; k++) sacc[c][k] = 0.f;

#pragma unroll
    for (int kk = 0; kk < 8; kk++) {
#pragma unroll
      for (int np = 0; np < 4; np++) {
        uint32_t bh[4];
        uint32_t boff = (uint32_t)(np * (16 * TRS) + kk * 32);
        LDSM_X4(bh[0], bh[1], bh[2], bh[3], aBh + boff);
        mma_f16(sacc[2 * np], ahf[kk], bh[0], bh[1]);
        mma_f16(sacc[2 * np], alf[kk], bh[0], bh[1]);
        mma_f16(sacc[2 * np + 1], ahf[kk], bh[2], bh[3]);
        mma_f16(sacc[2 * np + 1], alf[kk], bh[2], bh[3]);
      }
    }

    // ---- leakyrelu + mask -> log2 args; online max; vote-gated rescale ----
#pragma unroll
    for (int n = 0; n < 8; n++) {
      int2 mA = am[n];
      int2 mB = am[n + 8];
      float s0 = sacc[n][0], s1 = sacc[n][1], s2 = sacc[n][2], s3v = sacc[n][3];
      float a0 = fmaxf(s0, ALPHA * s0) * LOG2E;
      float a1 = fmaxf(s1, ALPHA * s1) * LOG2E;
      float a2 = fmaxf(s2, ALPHA * s2) * LOG2E;
      float a3 = fmaxf(s3v, ALPHA * s3v) * LOG2E;
      sacc[n][0] = (mA.x > 0) ? a0 : MASKV;
      sacc[n][1] = (mA.y > 0) ? a1 : MASKV;
      sacc[n][2] = (mB.x > 0) ? a2 : MASKV;
      sacc[n][3] = (mB.y > 0) ? a3 : MASKV;
    }
    {
      float mt0 = MASKV, mt1 = MASKV;
#pragma unroll
      for (int n = 0; n < 8; n++) {
        mt0 = fmaxf(mt0, fmaxf(sacc[n][0], sacc[n][1]));
        mt1 = fmaxf(mt1, fmaxf(sacc[n][2], sacc[n][3]));
      }
      mt0 = fmaxf(mt0, __shfl_xor_sync(0xffffffffu, mt0, 1));
      mt0 = fmaxf(mt0, __shfl_xor_sync(0xffffffffu, mt0, 2));
      mt1 = fmaxf(mt1, __shfl_xor_sync(0xffffffffu, mt1, 1));
      mt1 = fmaxf(mt1, __shfl_xor_sync(0xffffffffu, mt1, 2));
      float m0n = fmaxf(m0, mt0);
      float m1n = fmaxf(m1, mt1);
      bool need = (m0n > m0) || (m1n > m1);
      if (__any_sync(0xffffffffu, need)) {
        float sc0 = ex2f(m0 - m0n);
        float sc1 = ex2f(m1 - m1n);
#pragma unroll
        for (int c = 0; c < 16; c++) {
          oacc[c][0] *= sc0; oacc[c][1] *= sc0;
          oacc[c][2] *= sc1; oacc[c][3] *= sc1;
        }
        dacc[0] *= sc0; dacc[2] *= sc1;
      }
      m0 = m0n; m1 = m1n;
    }

    // ---- P = ex2(arg - m) -> fp16 fragments -> den MMA + PV ----
#pragma unroll
    for (int kk = 0; kk < 4; kk++) {
      uint32_t pw[4];
#pragma unroll
      for (int cp = 0; cp < 2; cp++) {
        int n = 2 * kk + cp;
        float p0 = ex2f(sacc[n][0] - m0);
        float p1 = ex2f(sacc[n][1] - m0);
        float p2 = ex2f(sacc[n][2] - m1);
        float p3 = ex2f(sacc[n][3] - m1);
        pw[2 * cp + 0] = pack_h2(p0, p1);
        pw[2 * cp + 1] = pack_h2(p2, p3);
      }
      mma_f16(dacc, pw, bones, bones);   // den += P @ ones (col 0)
#pragma unroll
      for (int cp = 0; cp < 8; cp++) {
        uint32_t vv[4];
        uint32_t voff = (uint32_t)(kk * (16 * TRS) + cp * 32);
        LDSM_X4T(vv[0], vv[1], vv[2], vv[3], aVh + voff);
        mma_f16(oacc[2 * cp], pw, vv[0], vv[1]);
        mma_f16(oacc[2 * cp + 1], pw, vv[2], vv[3]);
      }
    }
    s3 = (s3 == 2) ? 0 : s3 + 1;
  }

  // ---- epilogue: den (col 0 lives in tig==0 lanes) + m + O partials ----
  if (tig == 0) {
    gDen[(size_t)blockIdx.y * NN + row0] = dacc[0];
    gDen[(size_t)blockIdx.y * NN + row0 + 8] = dacc[2];
    gM[(size_t)blockIdx.y * NN + row0] = m0;
    gM[(size_t)blockIdx.y * NN + row0 + 8] = m1;
  }
  {
    size_t p0 = ((size_t)blockIdx.y * NN + row0) * 64;
    size_t p8 = ((size_t)blockIdx.y * NN + row0 + 8) * 64;
#pragma unroll
    for (int c = 0; c < 16; c++) {
      gNum2[p0 + c * 4 + tig] = pack_h2(oacc[c][0], oacc[c][1]);
      gNum2[p8 + c * 4 + tig] = pack_h2(oacc[c][2], oacc[c][3]);
    }
  }
}

// ---------------------------------------------------------------------------
// Kernel C: combine half2 split partials with per-split max weights (log2),
// divide, ELU. 4 cols/thread (grid 1024 for occupancy).
// ---------------------------------------------------------------------------
__global__ __launch_bounds__(256) void reduce_kernel(float* __restrict__ out) {
  int idx = blockIdx.x * 256 + threadIdx.x;   // over N*D/4 = 262144
  int row = idx >> 5;
  int cc = (idx & 31) * 2;                    // half2 index (2 half2 = 4 cols)
  float ms[SPLITS];
  float M = -1e30f;
#pragma unroll
  for (int s = 0; s < SPLITS; s++) {
    ms[s] = gM[(size_t)s * NN + row];
    M = fmaxf(M, ms[s]);
  }
  float acc[4];
#pragma unroll
  for (int i = 0; i < 4; i++) acc[i] = 0.f;
  float den = 0.f;
#pragma unroll
  for (int s = 0; s < SPLITS; s++) {
    float wgt = ex2f(ms[s] - M);
    uint2 v = *(const uint2*)&gNum2[((size_t)s * NN + row) * 64 + cc];
    float2 f0 = __half22float2(*reinterpret_cast<__half2*>(&v.x));
    float2 f1 = __half22float2(*reinterpret_cast<__half2*>(&v.y));
    acc[0] += wgt * f0.x; acc[1] += wgt * f0.y;
    acc[2] += wgt * f1.x; acc[3] += wgt * f1.y;
    den += gDen[(size_t)s * NN + row] * wgt;
  }
  float inv = 1.f / den;
  float o[4];
#pragma unroll
  for (int i = 0; i < 4; i++) {
    float h = acc[i] * inv;
    o[i] = (h > 0.f) ? h : expm1f(h);
  }
  *(float4*)(out + (size_t)row * DD + cc * 2) = make_float4(o[0], o[1], o[2], o[3]);
}

// ---------------------------------------------------------------------------
extern "C" void kernel_launch(void* const* d_in, const int* in_sizes, int n_in,
                              void* d_out, int out_size) {
  const float* inp = (const float*)d_in[0];
  const int* adj = (const int*)d_in[1];
  const float* W = (const float*)d_in[2];
  const float* W2 = (const float*)d_in[3];
  const float* W3 = (const float*)d_in[4];
  float* out = (float*)d_out;

  split_kernel<<<4288, 256>>>(inp, W, W2, W3);

  cudaFuncSetAttribute(proj_kernel, cudaFuncAttributeMaxDynamicSharedMemorySize,
                       PSMEM);
  proj_kernel<<<dim3(NN / 64, 3), 128, PSMEM>>>();

  cudaFuncSetAttribute(attn_kernel, cudaFuncAttributeMaxDynamicSharedMemorySize,
                       SMEM_BYTES);
  attn_kernel<<<dim3(NN / BM, SPLITS), 256, SMEM_BYTES>>>(adj);

  reduce_kernel<<<(NN * DD) / 1024, 256>>>(out);
}